// round 13
// baseline (speedup 1.0000x reference)
#include <cuda_runtime.h>
#include <cuda_fp16.h>
#include <cstdint>

// ParallelEmbedding: out[t,:] = W[x[t],:] + A[x[t],:] @ B
// NT=16384, DIM=1024, RANK=256.
// One CTA = 64 tokens x ALL 1024 dims (8 internal N-tiles). A staged once
// (fp16 SMEM), B double-buffered via cp.async, per-tile fused W epilogue.
// Grid = 256 CTAs -> whole problem resident in one wave.

#define NT     16384
#define DIM    1024
#define RANK   256
#define BM     64
#define TILE_N 128
#define NTILES (DIM / TILE_N)    // 8
#define KCH    64
#define NCH    (RANK / KCH)      // 4
#define NITER  (NTILES * NCH)    // 32

#define SMEM_TOKS 0              // 64 * 4 B
#define SMEM_A    1024           // 64 rows * 512 B = 32 KB (fp16, swizzled)
#define SMEM_B    33792          // 2 bufs * 16 KB
#define BBUF      16384
#define SMEM_TOTAL 66560

#define SW128(off) ((off) ^ (((off) >> 3) & 0x70))

__device__ __half g_BT[DIM * RANK];   // B^T fp16, [DIM][RANK] row-major

__device__ __forceinline__ uint32_t smem_u32(const void* p) {
    uint32_t a;
    asm("{ .reg .u64 t; cvta.to.shared.u64 t, %1; cvt.u32.u64 %0, t; }"
        : "=r"(a) : "l"(p));
    return a;
}
__device__ __forceinline__ void ldsm4(uint32_t* r, uint32_t addr) {
    asm volatile("ldmatrix.sync.aligned.m8n8.x4.shared.b16 {%0,%1,%2,%3}, [%4];"
                 : "=r"(r[0]), "=r"(r[1]), "=r"(r[2]), "=r"(r[3]) : "r"(addr));
}
__device__ __forceinline__ void mma_fp16(float* c, const uint32_t* a,
                                         const uint32_t* b) {
    asm volatile(
        "mma.sync.aligned.m16n8k16.row.col.f32.f16.f16.f32 "
        "{%0,%1,%2,%3}, {%4,%5,%6,%7}, {%8,%9}, {%0,%1,%2,%3};"
        : "+f"(c[0]), "+f"(c[1]), "+f"(c[2]), "+f"(c[3])
        : "r"(a[0]), "r"(a[1]), "r"(a[2]), "r"(a[3]), "r"(b[0]), "r"(b[1]));
}
__device__ __forceinline__ uint32_t packh(float a, float b) {
    __half2 t = __halves2half2(__float2half(a), __float2half(b));
    return *reinterpret_cast<uint32_t*>(&t);
}
__device__ __forceinline__ void cp_async16(uint32_t dst, const void* src) {
    asm volatile("cp.async.cg.shared.global [%0], [%1], 16;"
                 :: "r"(dst), "l"(src) : "memory");
}
#define CP_COMMIT() asm volatile("cp.async.commit_group;" ::: "memory")
#define CP_WAIT0()  asm volatile("cp.async.wait_group 0;" ::: "memory")

// ---------------- Prep: B[K][N] fp32 -> B^T fp16 [N][K] ----------------
__global__ void prep_B_kernel(const float* __restrict__ B) {
    __shared__ float tile[32][33];
    const int tx = threadIdx.x & 31;
    const int ty = threadIdx.x >> 5;
    const int k0 = blockIdx.x * 32;
    const int n0 = blockIdx.y * 32;
    #pragma unroll
    for (int i = 0; i < 4; ++i)
        tile[ty + 8 * i][tx] = B[(size_t)(k0 + ty + 8 * i) * DIM + n0 + tx];
    __syncthreads();
    #pragma unroll
    for (int i = 0; i < 4; ++i) {
        int nl = ty + 8 * i;
        g_BT[(size_t)(n0 + nl) * RANK + k0 + tx] = __float2half(tile[tx][nl]);
    }
}

// ---------------- Main kernel ----------------
__global__ __launch_bounds__(256, 2)
void lora_embed_hmma_kernel(const int*   __restrict__ x,
                            const float* __restrict__ W,
                            const float* __restrict__ A,
                            float*       __restrict__ out)
{
    extern __shared__ char smem[];
    const uint32_t sb  = smem_u32(smem);
    const int tid = threadIdx.x;
    const int wid = tid >> 5;
    const int lid = tid & 31;
    const int wm  = wid >> 1;                 // 0..3 : 16 rows each
    const int wn  = wid & 1;                  // 0..1 : 64 cols of 128-col tile
    const int m0  = blockIdx.x * BM;

    int* toks = reinterpret_cast<int*>(smem + SMEM_TOKS);
    if (tid < BM) toks[tid] = x[m0 + tid];
    __syncthreads();

    // --- Stage A once: 64 rows x 256 k fp32 -> fp16, 512B rows, SW128/128B-blk ---
    #pragma unroll
    for (int it = 0; it < 16; ++it) {
        int f4  = it * 256 + tid;             // 0..4095 float4s
        int row = f4 >> 6;                    // 0..63
        int kb4 = (f4 & 63) << 2;             // k element 0..252
        const float4 v = *reinterpret_cast<const float4*>(
            A + (size_t)toks[row] * RANK + kb4);
        uint32_t kbyte = (uint32_t)kb4 * 2;   // 0..504
        uint32_t addr = (uint32_t)row * 512 + (kbyte & ~127u) +
                        ((kbyte & 127u) ^ (((uint32_t)row & 7u) << 4));
        *reinterpret_cast<uint2*>(smem + SMEM_A + addr) =
            make_uint2(packh(v.x, v.y), packh(v.z, v.w));
    }

    // --- cp.async B issue for linear iteration j (tile j>>2, chunk j&3) ---
    auto issue_B = [&](int j) {
        const int nt = j >> 2;
        const int c  = j & 3;
        const uint32_t bufo = (uint32_t)(j & 1) * BBUF;
        #pragma unroll
        for (int it = 0; it < 4; ++it) {
            int u = it * 256 + tid;           // 0..1023 16B units
            int r = u >> 3;                   // n row 0..127
            int jj = u & 7;
            const __half* src = g_BT + (size_t)(nt * TILE_N + r) * RANK
                                      + c * KCH + jj * 8;
            cp_async16(sb + SMEM_B + bufo + SW128((uint32_t)(r * 128 + jj * 16)),
                       src);
        }
        CP_COMMIT();
    };
    issue_B(0);

    // --- Fragment addressing (SW128 within 128B k-blocks) ---
    const int t  = lid >> 3;
    const int r8 = lid & 7;
    const int arow = wm * 16 + r8 + (t & 1) * 8;          // 0..63
    const uint32_t a_base = (uint32_t)arow * 512;
    const uint32_t a_xr   = (uint32_t)(arow & 7);
    const int a_kbh = t >> 1;
    uint32_t b_rowoff[4], b_xr[4];
    #pragma unroll
    for (int nfp = 0; nfp < 4; ++nfp) {
        int nrow = wn * 64 + nfp * 16 + (t >> 1) * 8 + r8;
        b_rowoff[nfp] = (uint32_t)nrow * 128;
        b_xr[nfp]     = (uint32_t)(nrow & 7);
    }
    const int b_kbh = t & 1;
    const int cl = (lid & 3) * 2;

    float acc[8][4];
    #pragma unroll
    for (int j = 0; j < 8; ++j)
        #pragma unroll
        for (int q = 0; q < 4; ++q) acc[j][q] = 0.0f;

    for (int i = 0; i < NITER; ++i) {
        const int c = i & 3;
        CP_WAIT0();                 // B_i landed
        __syncthreads();            // all warps past compute i-1 -> buf free
        if (i + 1 < NITER) issue_B(i + 1);   // overlaps compute i
        const uint32_t bufo = (uint32_t)(i & 1) * BBUF;

        #pragma unroll
        for (int ks = 0; ks < 4; ++ks) {
            uint32_t ah[4];
            {
                uint32_t kbu = (uint32_t)(2 * ks + a_kbh);
                ldsm4(ah, sb + SMEM_A + a_base + (uint32_t)c * 128 +
                          ((kbu ^ a_xr) << 4));
            }
            #pragma unroll
            for (int nfp = 0; nfp < 4; ++nfp) {
                uint32_t kb  = (uint32_t)(2 * ks + b_kbh);
                uint32_t bh[4];
                ldsm4(bh, sb + SMEM_B + bufo + b_rowoff[nfp] +
                          ((kb ^ b_xr[nfp]) << 4));
                mma_fp16(acc[nfp * 2 + 0], ah, bh + 0);
                mma_fp16(acc[nfp * 2 + 1], ah, bh + 2);
            }
        }

        if (c == 3) {
            // --- Per-tile epilogue: fused W gather + store, then reset acc ---
            const int nt = i >> 2;
            const int ncol = nt * TILE_N + wn * 64 + cl;
            const int rbase = wm * 16 + (lid >> 2);
            #pragma unroll
            for (int h = 0; h < 2; ++h) {
                int row = rbase + h * 8;
                const float* wrow = W + (size_t)toks[row] * DIM + ncol;
                float*       orow = out + (size_t)(m0 + row) * DIM + ncol;
                #pragma unroll
                for (int nf = 0; nf < 8; ++nf) {
                    float2 wv = __ldcs(
                        reinterpret_cast<const float2*>(wrow + nf * 8));
                    float2 ov;
                    ov.x = acc[nf][2 * h + 0] + wv.x;
                    ov.y = acc[nf][2 * h + 1] + wv.y;
                    __stcs(reinterpret_cast<float2*>(orow + nf * 8), ov);
                }
            }
            #pragma unroll
            for (int j = 0; j < 8; ++j)
                #pragma unroll
                for (int q = 0; q < 4; ++q) acc[j][q] = 0.0f;
        }
    }
}

extern "C" void kernel_launch(void* const* d_in, const int* in_sizes, int n_in,
                              void* d_out, int out_size) {
    const int*   x = (const int*)  d_in[0];
    const float* W = (const float*)d_in[1];
    const float* A = (const float*)d_in[2];
    const float* B = (const float*)d_in[3];
    float* out = (float*)d_out;

    (void)cudaFuncSetAttribute(lora_embed_hmma_kernel,
                               cudaFuncAttributeMaxDynamicSharedMemorySize,
                               SMEM_TOTAL);

    prep_B_kernel<<<dim3(RANK / 32, DIM / 32), 256>>>(B);
    lora_embed_hmma_kernel<<<dim3(NT / BM), 256, SMEM_TOTAL>>>(x, W, A, out);
}

// round 15
// speedup vs baseline: 1.9829x; 1.9829x over previous
#include <cuda_runtime.h>
#include <cuda_fp16.h>
#include <cstdint>

// ParallelEmbedding: out[t,:] = W[x[t],:] + A[x[t],:] @ B
// NT=16384, DIM=1024, RANK=256.
// fp16 mma.sync GEMM (fp32 accum). R9 structure (128x128 CTA tiles, 4 K-chunks,
// double-buffered SMEM) + grid swapped for A L2 reuse + B via cp.async
// double-buffer + W mf0-half prefetch overlapping the last chunk's MMAs.

#define NT    16384
#define DIM   1024
#define RANK  256
#define BM    128
#define BN    128
#define KCH   64
#define NCHUNK (RANK / KCH)

#define SMEM_TOKS 0
#define SMEM_AH   1024
#define SMEM_BH   17408
#define BUF_STRIDE 32768
#define SMEM_TOTAL 66560

#define SW128(off) ((off) ^ (((off) >> 3) & 0x70))

__device__ __half g_BT[DIM * RANK];   // B^T fp16, [DIM][RANK] row-major

__device__ __forceinline__ uint32_t smem_u32(const void* p) {
    uint32_t a;
    asm("{ .reg .u64 t; cvta.to.shared.u64 t, %1; cvt.u32.u64 %0, t; }"
        : "=r"(a) : "l"(p));
    return a;
}
__device__ __forceinline__ void ldsm4(uint32_t* r, uint32_t addr) {
    asm volatile("ldmatrix.sync.aligned.m8n8.x4.shared.b16 {%0,%1,%2,%3}, [%4];"
                 : "=r"(r[0]), "=r"(r[1]), "=r"(r[2]), "=r"(r[3]) : "r"(addr));
}
__device__ __forceinline__ void mma_fp16(float* c, const uint32_t* a,
                                         const uint32_t* b) {
    asm volatile(
        "mma.sync.aligned.m16n8k16.row.col.f32.f16.f16.f32 "
        "{%0,%1,%2,%3}, {%4,%5,%6,%7}, {%8,%9}, {%0,%1,%2,%3};"
        : "+f"(c[0]), "+f"(c[1]), "+f"(c[2]), "+f"(c[3])
        : "r"(a[0]), "r"(a[1]), "r"(a[2]), "r"(a[3]), "r"(b[0]), "r"(b[1]));
}
__device__ __forceinline__ uint32_t packh(float a, float b) {
    __half2 t = __halves2half2(__float2half(a), __float2half(b));
    return *reinterpret_cast<uint32_t*>(&t);
}
__device__ __forceinline__ void cp_async16(uint32_t dst, const void* src) {
    asm volatile("cp.async.cg.shared.global [%0], [%1], 16;"
                 :: "r"(dst), "l"(src) : "memory");
}
#define CP_COMMIT() asm volatile("cp.async.commit_group;" ::: "memory")
#define CP_WAIT0()  asm volatile("cp.async.wait_group 0;" ::: "memory")

// ---------------- Prep: B[K][N] fp32 -> B^T fp16 [N][K] ----------------
__global__ void prep_B_kernel(const float* __restrict__ B) {
    __shared__ float tile[32][33];
    const int tx = threadIdx.x & 31;
    const int ty = threadIdx.x >> 5;
    const int k0 = blockIdx.x * 32;
    const int n0 = blockIdx.y * 32;
    #pragma unroll
    for (int i = 0; i < 4; ++i)
        tile[ty + 8 * i][tx] = B[(size_t)(k0 + ty + 8 * i) * DIM + n0 + tx];
    __syncthreads();
    #pragma unroll
    for (int i = 0; i < 4; ++i) {
        int nl = ty + 8 * i;
        g_BT[(size_t)(n0 + nl) * RANK + k0 + tx] = __float2half(tile[tx][nl]);
    }
}

// ---------------- Main kernel ----------------
__global__ __launch_bounds__(256, 2)
void lora_embed_hmma_kernel(const int*   __restrict__ x,
                            const float* __restrict__ W,
                            const float* __restrict__ A,
                            float*       __restrict__ out)
{
    extern __shared__ char smem[];
    const uint32_t sb  = smem_u32(smem);
    const int tid = threadIdx.x;
    const int wid = tid >> 5;
    const int lid = tid & 31;
    const int wm  = wid >> 1;
    const int wn  = wid & 1;
    // Grid swapped: x = N-tile (8), y = M-tile (128) -> same-M CTAs adjacent.
    const int n0  = blockIdx.x * BN;
    const int m0  = blockIdx.y * BM;

    // --- Issue B chunk 0 cp.async immediately (no dependency on toks) ---
    {
        #pragma unroll
        for (int it = 0; it < 4; ++it) {
            int u = it * 256 + tid;
            int r = u >> 3;
            int j = u & 7;
            cp_async16(sb + SMEM_BH + SW128((uint32_t)(r * 128 + j * 16)),
                       g_BT + (size_t)(n0 + r) * RANK + j * 8);
        }
        CP_COMMIT();
    }

    int* toks = reinterpret_cast<int*>(smem + SMEM_TOKS);
    if (tid < BM) toks[tid] = x[m0 + tid];
    __syncthreads();

    float acc[2][8][4];
    #pragma unroll
    for (int i = 0; i < 2; ++i)
        #pragma unroll
        for (int j = 0; j < 8; ++j)
            #pragma unroll
            for (int q = 0; q < 4; ++q) acc[i][j][q] = 0.0f;

    // --- ldmatrix lane addressing (SW128: kb' = kb ^ (row&7)) ---
    const int t  = lid >> 3;
    const int r8 = lid & 7;
    uint32_t a_rowoff[2], a_xr[2];
    #pragma unroll
    for (int mf = 0; mf < 2; ++mf) {
        int row = wm * 32 + mf * 16 + r8 + (t & 1) * 8;
        a_rowoff[mf] = (uint32_t)row * 128;
        a_xr[mf]     = (uint32_t)(row & 7);
    }
    const int a_kbh = t >> 1;
    uint32_t b_rowoff[4], b_xr[4];
    #pragma unroll
    for (int nfp = 0; nfp < 4; ++nfp) {
        int nrow = wn * 64 + nfp * 16 + (t >> 1) * 8 + r8;
        b_rowoff[nfp] = (uint32_t)nrow * 128;
        b_xr[nfp]     = (uint32_t)(nrow & 7);
    }
    const int b_kbh = t & 1;
    const int cl = (lid & 3) * 2;

    // --- A gather addressing + chunk-0 register prefetch ---
    const int kbf = (tid & 15) << 2;
    const float* aptr[8];
    #pragma unroll
    for (int it = 0; it < 8; ++it) {
        int row = it * 16 + (tid >> 4);
        aptr[it] = A + (size_t)toks[row] * RANK + kbf;
    }
    float4 av[8];
    #pragma unroll
    for (int it = 0; it < 8; ++it) av[it] = *reinterpret_cast<const float4*>(aptr[it]);

    float2 w0[2][8];   // W prefetch, mf=0 half (written in last chunk)

    #pragma unroll
    for (int c = 0; c < NCHUNK; ++c) {
        const uint32_t bufo = (uint32_t)(c & 1) * BUF_STRIDE;

        // --- STS A chunk c (fp32 -> fp16), SW128 ---
        #pragma unroll
        for (int it = 0; it < 8; ++it) {
            int row = it * 16 + (tid >> 4);
            uint32_t off = SW128((uint32_t)(row * 128 + kbf * 2));
            *reinterpret_cast<uint2*>(smem + SMEM_AH + bufo + off) =
                make_uint2(packh(av[it].x, av[it].y), packh(av[it].z, av[it].w));
        }

        CP_WAIT0();          // B_c landed
        __syncthreads();     // all warps past compute c-1; tiles of c ready

        if (c + 1 < NCHUNK) {
            // Prefetch A chunk c+1 (registers) — overlaps compute c.
            #pragma unroll
            for (int it = 0; it < 8; ++it)
                av[it] = *reinterpret_cast<const float4*>(aptr[it] + (c + 1) * KCH);
            // Issue B chunk c+1 cp.async into the other buffer.
            const int k0n = (c + 1) * KCH;
            const uint32_t bufn = (uint32_t)((c + 1) & 1) * BUF_STRIDE;
            #pragma unroll
            for (int it = 0; it < 4; ++it) {
                int u = it * 256 + tid;
                int r = u >> 3;
                int j = u & 7;
                cp_async16(sb + SMEM_BH + bufn + SW128((uint32_t)(r * 128 + j * 16)),
                           g_BT + (size_t)(n0 + r) * RANK + k0n + j * 8);
            }
            CP_COMMIT();
        } else {
            // Last chunk: prefetch W mf=0 half — overlaps compute c=3.
            #pragma unroll
            for (int h = 0; h < 2; ++h) {
                int row = wm * 32 + (lid >> 2) + h * 8;
                const float* wrow =
                    W + (size_t)toks[row] * DIM + n0 + wn * 64 + cl;
                #pragma unroll
                for (int nf = 0; nf < 8; ++nf)
                    w0[h][nf] =
                        __ldcs(reinterpret_cast<const float2*>(wrow + nf * 8));
            }
        }

        // --- Compute chunk c ---
        #pragma unroll
        for (int ks = 0; ks < 4; ++ks) {
            uint32_t ah[2][4];
            #pragma unroll
            for (int mf = 0; mf < 2; ++mf) {
                uint32_t kb  = (uint32_t)(2 * ks + a_kbh);
                uint32_t off = a_rowoff[mf] + ((kb ^ a_xr[mf]) << 4);
                ldsm4(ah[mf], sb + SMEM_AH + bufo + off);
            }
            #pragma unroll
            for (int nfp = 0; nfp < 4; ++nfp) {
                uint32_t kb  = (uint32_t)(2 * ks + b_kbh);
                uint32_t off = b_rowoff[nfp] + ((kb ^ b_xr[nfp]) << 4);
                uint32_t bh[4];
                ldsm4(bh, sb + SMEM_BH + bufo + off);
                #pragma unroll
                for (int h = 0; h < 2; ++h) {
                    int nf = nfp * 2 + h;
                    mma_fp16(acc[0][nf], ah[0], bh + 2 * h);
                    mma_fp16(acc[1][nf], ah[1], bh + 2 * h);
                }
            }
        }
    }

    // --- Epilogue: mf=0 uses prefetched W; mf=1 loads batch here ---
    #pragma unroll
    for (int h = 0; h < 2; ++h) {
        int row = wm * 32 + (lid >> 2) + h * 8;
        float* orow = out + (size_t)(m0 + row) * DIM + n0 + wn * 64 + cl;
        #pragma unroll
        for (int nf = 0; nf < 8; ++nf) {
            float2 ov;
            ov.x = acc[0][nf][2 * h + 0] + w0[h][nf].x;
            ov.y = acc[0][nf][2 * h + 1] + w0[h][nf].y;
            __stcs(reinterpret_cast<float2*>(orow + nf * 8), ov);
        }
    }
    {
        float2 w1[2][8];
        #pragma unroll
        for (int h = 0; h < 2; ++h) {
            int row = wm * 32 + 16 + (lid >> 2) + h * 8;
            const float* wrow = W + (size_t)toks[row] * DIM + n0 + wn * 64 + cl;
            #pragma unroll
            for (int nf = 0; nf < 8; ++nf)
                w1[h][nf] = __ldcs(reinterpret_cast<const float2*>(wrow + nf * 8));
        }
        #pragma unroll
        for (int h = 0; h < 2; ++h) {
            int row = wm * 32 + 16 + (lid >> 2) + h * 8;
            float* orow = out + (size_t)(m0 + row) * DIM + n0 + wn * 64 + cl;
            #pragma unroll
            for (int nf = 0; nf < 8; ++nf) {
                float2 ov;
                ov.x = acc[1][nf][2 * h + 0] + w1[h][nf].x;
                ov.y = acc[1][nf][2 * h + 1] + w1[h][nf].y;
                __stcs(reinterpret_cast<float2*>(orow + nf * 8), ov);
            }
        }
    }
}

extern "C" void kernel_launch(void* const* d_in, const int* in_sizes, int n_in,
                              void* d_out, int out_size) {
    const int*   x = (const int*)  d_in[0];
    const float* W = (const float*)d_in[1];
    const float* A = (const float*)d_in[2];
    const float* B = (const float*)d_in[3];
    float* out = (float*)d_out;

    (void)cudaFuncSetAttribute(lora_embed_hmma_kernel,
                               cudaFuncAttributeMaxDynamicSharedMemorySize,
                               SMEM_TOTAL);

    prep_B_kernel<<<dim3(RANK / 32, DIM / 32), 256>>>(B);
    lora_embed_hmma_kernel<<<dim3(DIM / BN, NT / BM), 256, SMEM_TOTAL>>>(x, W, A, out);
}